// round 13
// baseline (speedup 1.0000x reference)
#include <cuda_runtime.h>
#include <cuda_fp16.h>
#include <cstdint>

// ---------------------------------------------------------------------------
// FeatureAttentionPerFeature — mma.sync pure fp16
//   scores[b,f] = feat_f[b] . (Wk_f^T q)/sqrt(128)
//   w = softmax_f(scores)
//   combined = (w-scaled concat feats) @ Wv_all^T
// Output: [ combined (B*128) | attn_weights (B*8) ]
// R13: MBLK=64, warp tile 32x32, launch_bounds(256,3) -> 24 warps/SM
// ---------------------------------------------------------------------------

#define NF     8
#define HID    128
#define KTOT   1664
#define BATCHN 32768
#define MBLK   64
#define KCH    128
#define NCH    (KTOT/KCH)    // 13
#define NTHR   256
#define RSTRIDE 272          // smem row stride BYTES (256 data + 16 pad)

__device__ constexpr int DIMS_C[NF]   = {32, 64, 96, 128, 192, 256, 384, 512};
__device__ constexpr int OFFS_C[NF+1] = {0, 32, 96, 192, 320, 512, 768, 1152, 1664};
__constant__ int gDIMS[NF]   = {32, 64, 96, 128, 192, 256, 384, 512};
__constant__ int gOFFS[NF+1] = {0, 32, 96, 192, 320, 512, 768, 1152, 1664};

// device scratch
__device__ float g_c[KTOT];
__device__ __half g_Bh[HID * KTOT];   // Wv (fp16), [n][k] k-major

struct Ptrs {
    const float* feat[NF];
    const float* Wk[NF];
    const float* Wv[NF];
    const float* q;
};

// ---------------- helpers ----------------
__device__ __forceinline__ uint32_t smem_u32(const void* p) {
    uint32_t a;
    asm("{ .reg .u64 t; cvta.to.shared.u64 t, %1; cvt.u32.u64 %0, t; }" : "=r"(a) : "l"(p));
    return a;
}
__device__ __forceinline__ void ldsm_x4(uint32_t* r, uint32_t a) {
    asm volatile("ldmatrix.sync.aligned.m8n8.x4.shared.b16 {%0,%1,%2,%3}, [%4];"
                 : "=r"(r[0]), "=r"(r[1]), "=r"(r[2]), "=r"(r[3]) : "r"(a));
}
__device__ __forceinline__ void mma_fp16(float* c, const uint32_t* a, const uint32_t* b) {
    asm volatile(
        "mma.sync.aligned.m16n8k16.row.col.f32.f16.f16.f32 "
        "{%0,%1,%2,%3}, {%4,%5,%6,%7}, {%8,%9}, {%0,%1,%2,%3};"
        : "+f"(c[0]), "+f"(c[1]), "+f"(c[2]), "+f"(c[3])
        : "r"(a[0]), "r"(a[1]), "r"(a[2]), "r"(a[3]), "r"(b[0]), "r"(b[1]));
}
__device__ __forceinline__ int ffind(int k) {
    int f = 7;
    if (k < 1152) f = 6;
    if (k < 768)  f = 5;
    if (k < 512)  f = 4;
    if (k < 320)  f = 3;
    if (k < 192)  f = 2;
    if (k < 96)   f = 1;
    if (k < 32)   f = 0;
    return f;
}

// ---------------- SMEM layout (dynamic, bytes) ----------------
#define OFF_CS  0                        // 1664*4 = 6656
#define OFF_WS  6656                     // 64*8*4 = 2048
#define OFF_AH  8704                     // 64*272 = 17408 (fp16 A tile)
#define OFF_BH  (OFF_AH + 17408)         // 128*272 = 34816
#define SMEM_TOT (OFF_BH + 34816)        // 60928  (3 CTAs/SM: 182784 < 228K)

// ---------------------------------------------------------------------------
// prep: c vector (warp per k) + fp16 pack of Wv into [n][k]
// ---------------------------------------------------------------------------
__global__ void prep_kernel(Ptrs p) {
    int tid = blockIdx.x * blockDim.x + threadIdx.x;

    if (tid < KTOT * 32) {
        int k = tid >> 5, ln = tid & 31;
        int f = ffind(k);
        int j = k - gOFFS[f];
        int d = gDIMS[f];
        const float* W = p.Wk[f];
        float s = 0.f;
        #pragma unroll
        for (int h = ln; h < HID; h += 32) s += W[h * d + j] * p.q[h];
        #pragma unroll
        for (int o = 16; o; o >>= 1) s += __shfl_xor_sync(0xffffffffu, s, o);
        if (ln == 0) g_c[k] = s * 0.08838834764831845f;
    }

    if (tid < HID * KTOT) {
        int n = tid / KTOT;
        int k = tid % KTOT;
        int f = ffind(k);
        int j = k - gOFFS[f];
        g_Bh[tid] = __float2half_rn(p.Wv[f][n * gDIMS[f] + j]);
    }
}

// ---------------------------------------------------------------------------
// main kernel: grid 512 x 256 threads, 3 CTAs/SM (reg-capped)
// ---------------------------------------------------------------------------
__global__ void __launch_bounds__(NTHR, 3)
main_kernel(Ptrs p, float* __restrict__ out) {
    extern __shared__ char smem[];
    const uint32_t sb = smem_u32(smem);
    const int t    = threadIdx.x;
    const int lane = t & 31;
    const int wid  = t >> 5;
    const int wm   = wid >> 2;          // 0..1  (32 rows each)
    const int wn   = wid & 3;           // 0..3  (32 cols each)
    const int row0 = blockIdx.x * MBLK;

    float* cs   = (float*)(smem + OFF_CS);
    float* ws_s = (float*)(smem + OFF_WS);

    for (int i = t; i < KTOT; i += NTHR) cs[i] = g_c[i];
    __syncthreads();

    // ---- phase 1: warp-per-row scores + softmax (8 rows per warp) ----
    {
        #pragma unroll 1
        for (int rr = 0; rr < 8; rr++) {
            const int lrow = wid * 8 + rr;
            const int row  = row0 + lrow;
            float sc[NF];
            #pragma unroll
            for (int f = 0; f < NF; f++) {
                const int d = DIMS_C[f];
                float s = 0.f;
                #pragma unroll
                for (int j0 = 0; j0 < d; j0 += 128) {
                    int j = j0 + lane * 4;
                    if (j < d) {
                        float4 a = *(const float4*)(p.feat[f] + (size_t)row * d + j);
                        float4 b = *(const float4*)(cs + OFFS_C[f] + j);
                        s += a.x * b.x + a.y * b.y + a.z * b.z + a.w * b.w;
                    }
                }
                sc[f] = s;
            }
            #pragma unroll
            for (int f = 0; f < NF; f++) {
                #pragma unroll
                for (int o = 16; o; o >>= 1)
                    sc[f] += __shfl_xor_sync(0xffffffffu, sc[f], o);
            }
            float m = sc[0];
            #pragma unroll
            for (int f = 1; f < NF; f++) m = fmaxf(m, sc[f]);
            float sum = 0.f;
            #pragma unroll
            for (int f = 0; f < NF; f++) { sc[f] = expf(sc[f] - m); sum += sc[f]; }
            const float inv = 1.f / sum;
            if (lane == 0) {
                float4 w0 = make_float4(sc[0] * inv, sc[1] * inv, sc[2] * inv, sc[3] * inv);
                float4 w1 = make_float4(sc[4] * inv, sc[5] * inv, sc[6] * inv, sc[7] * inv);
                *(float4*)(ws_s + lrow * NF)     = w0;
                *(float4*)(ws_s + lrow * NF + 4) = w1;
                float* ao = out + (size_t)BATCHN * HID + (size_t)row * NF;
                *(float4*)(ao)     = w0;
                *(float4*)(ao + 4) = w1;
            }
        }
    }

    // ---- mainloop ----
    float acc[2][4][4];
    #pragma unroll
    for (int mf = 0; mf < 2; mf++)
        #pragma unroll
        for (int nf = 0; nf < 4; nf++)
            #pragma unroll
            for (int r = 0; r < 4; r++) acc[mf][nf][r] = 0.f;

    // per-lane ldmatrix base offsets (bytes)
    const uint32_t aoff = (uint32_t)((wm * 32 + (lane & 15)) * RSTRIDE + (lane >> 4) * 16);
    const uint32_t boff = (uint32_t)((wn * 32 + ((lane >> 4) * 8) + (lane & 7)) * RSTRIDE +
                                     ((lane >> 3) & 1) * 16);
    const uint32_t sAh = sb + OFF_AH;
    const uint32_t sBh = sb + OFF_BH;

    for (int ch = 0; ch < NCH; ch++) {
        const int k0 = ch * KCH;
        __syncthreads();   // previous chunk's ldmatrix done; ws ready (iter 0)

        // --- A convert: 64 rows x 128 k, weighted fp16 ---
        #pragma unroll
        for (int it = 0; it < 4; it++) {
            int g   = it * 256 + t;        // 0..1023
            int row = g >> 4;
            int kq  = g & 15;              // 16 groups of 8 k
            int kg  = k0 + kq * 8;
            int f   = ffind(kg);
            int j   = kg - gOFFS[f];
            const float* src = p.feat[f] + (size_t)(row0 + row) * gDIMS[f] + j;
            float4 v0 = *(const float4*)src;
            float4 v1 = *(const float4*)(src + 4);
            float w = ws_s[row * NF + f];
            float x[8] = {v0.x * w, v0.y * w, v0.z * w, v0.w * w,
                          v1.x * w, v1.y * w, v1.z * w, v1.w * w};
            uint32_t h[4];
            #pragma unroll
            for (int q = 0; q < 4; q++) {
                __half b0 = __float2half_rn(x[2 * q]);
                __half b1 = __float2half_rn(x[2 * q + 1]);
                h[q] = (uint32_t)__half_as_ushort(b0) | ((uint32_t)__half_as_ushort(b1) << 16);
            }
            uint32_t off = (uint32_t)(row * RSTRIDE + kq * 16);
            *(uint4*)(smem + OFF_AH + off) = make_uint4(h[0], h[1], h[2], h[3]);
        }
        // --- B tile: copy from packed global (L2-resident) ---
        #pragma unroll
        for (int it = 0; it < 8; it++) {
            int g  = it * 256 + t;         // 0..2047
            int n  = g >> 4;
            int kq = g & 15;
            size_t goff = (size_t)n * KTOT + k0 + kq * 8;
            uint32_t off = (uint32_t)(n * RSTRIDE + kq * 16);
            *(uint4*)(smem + OFF_BH + off) = *(const uint4*)&g_Bh[goff];
        }
        __syncthreads();

        // --- tensor-core phase: 8 k16 steps ---
        #pragma unroll
        for (int ks = 0; ks < 8; ks++) {
            const uint32_t koff = ks * 32;   // 16 fp16 = 32 bytes
            uint32_t a[2][4];
            #pragma unroll
            for (int mf = 0; mf < 2; mf++)
                ldsm_x4(a[mf], sAh + aoff + mf * (16 * RSTRIDE) + koff);

            uint32_t bh[4][2];
            #pragma unroll
            for (int bq = 0; bq < 2; bq++) {
                uint32_t r[4];
                ldsm_x4(r, sBh + boff + bq * (16 * RSTRIDE) + koff);
                bh[bq * 2][0] = r[0]; bh[bq * 2][1] = r[1];
                bh[bq * 2 + 1][0] = r[2]; bh[bq * 2 + 1][1] = r[3];
            }
            #pragma unroll
            for (int mf = 0; mf < 2; mf++)
                #pragma unroll
                for (int nf = 0; nf < 4; nf++) mma_fp16(acc[mf][nf], a[mf], bh[nf]);
        }
    }

    // ---- epilogue: write combined ----
    #pragma unroll
    for (int mf = 0; mf < 2; mf++) {
        #pragma unroll
        for (int nf = 0; nf < 4; nf++) {
            int r0 = row0 + wm * 32 + mf * 16 + (lane >> 2);
            int c  = wn * 32 + nf * 8 + (lane & 3) * 2;
            *(float2*)(out + (size_t)r0 * HID + c) =
                make_float2(acc[mf][nf][0], acc[mf][nf][1]);
            *(float2*)(out + (size_t)(r0 + 8) * HID + c) =
                make_float2(acc[mf][nf][2], acc[mf][nf][3]);
        }
    }
}

// ---------------------------------------------------------------------------
extern "C" void kernel_launch(void* const* d_in, const int* in_sizes, int n_in,
                              void* d_out, int out_size) {
    static const int dims[NF] = {32, 64, 96, 128, 192, 256, 384, 512};
    Ptrs p;
    int wseen[NF] = {0};

    for (int i = 0; i < n_in; i++) {
        const float* ptr = (const float*)d_in[i];
        int s = in_sizes[i];
        if (s == HID) { p.q = ptr; continue; }
        bool matched = false;
        for (int f = 0; f < NF; f++)
            if (s == BATCHN * dims[f]) { p.feat[f] = ptr; matched = true; break; }
        if (matched) continue;
        for (int f = 0; f < NF; f++)
            if (s == HID * dims[f]) {
                if (!wseen[f]) { p.Wk[f] = ptr; wseen[f] = 1; }
                else           { p.Wv[f] = ptr; }
                break;
            }
    }

    cudaFuncSetAttribute(main_kernel, cudaFuncAttributeMaxDynamicSharedMemorySize, SMEM_TOT);

    prep_kernel<<<(HID * KTOT + 255) / 256, 256>>>(p);
    main_kernel<<<BATCHN / MBLK, NTHR, SMEM_TOT>>>(p, (float*)d_out);
}

// round 15
// speedup vs baseline: 1.1644x; 1.1644x over previous
#include <cuda_runtime.h>
#include <cuda_fp16.h>
#include <cstdint>

// ---------------------------------------------------------------------------
// FeatureAttentionPerFeature — mma.sync pure fp16
//   scores[b,f] = feat_f[b] . (Wk_f^T q)/sqrt(128)
//   w = softmax_f(scores)
//   combined = (w-scaled concat feats) @ Wv_all^T
// Output: [ combined (B*128) | attn_weights (B*8) ]
// R15 (on R12 base): mainloop consumes chunks in REVERSE (f7 first) for LIFO
// L2 reuse of phase-1 reads; convert loads use 32B ld.global.L2::evict_first
// (v4.b64 — the form this ptxas accepts) so streaming doesn't evict warm set.
// ---------------------------------------------------------------------------

#define NF     8
#define HID    128
#define KTOT   1664
#define BATCHN 32768
#define MBLK   128
#define KCH    128
#define NCH    (KTOT/KCH)    // 13
#define NTHR   256
#define RSTRIDE 272          // smem row stride BYTES (256 data + 16 pad)

__device__ constexpr int DIMS_C[NF]   = {32, 64, 96, 128, 192, 256, 384, 512};
__device__ constexpr int OFFS_C[NF+1] = {0, 32, 96, 192, 320, 512, 768, 1152, 1664};
__constant__ int gDIMS[NF]   = {32, 64, 96, 128, 192, 256, 384, 512};
__constant__ int gOFFS[NF+1] = {0, 32, 96, 192, 320, 512, 768, 1152, 1664};

// device scratch
__device__ float g_c[KTOT];
__device__ __half g_Bh[HID * KTOT];   // Wv (fp16), [n][k] k-major

struct Ptrs {
    const float* feat[NF];
    const float* Wk[NF];
    const float* Wv[NF];
    const float* q;
};

// ---------------- helpers ----------------
__device__ __forceinline__ uint32_t smem_u32(const void* p) {
    uint32_t a;
    asm("{ .reg .u64 t; cvta.to.shared.u64 t, %1; cvt.u32.u64 %0, t; }" : "=r"(a) : "l"(p));
    return a;
}
// 32-byte streaming load (8 floats), L2 evict_first — v4.b64 form
__device__ __forceinline__ void ldg8_stream(const float* p, float* x) {
    unsigned long long r0, r1, r2, r3;
    asm("ld.global.L2::evict_first.v4.b64 {%0,%1,%2,%3}, [%4];"
        : "=l"(r0), "=l"(r1), "=l"(r2), "=l"(r3) : "l"(p));
    x[0] = __uint_as_float((uint32_t)r0);  x[1] = __uint_as_float((uint32_t)(r0 >> 32));
    x[2] = __uint_as_float((uint32_t)r1);  x[3] = __uint_as_float((uint32_t)(r1 >> 32));
    x[4] = __uint_as_float((uint32_t)r2);  x[5] = __uint_as_float((uint32_t)(r2 >> 32));
    x[6] = __uint_as_float((uint32_t)r3);  x[7] = __uint_as_float((uint32_t)(r3 >> 32));
}
__device__ __forceinline__ void ldsm_x4(uint32_t* r, uint32_t a) {
    asm volatile("ldmatrix.sync.aligned.m8n8.x4.shared.b16 {%0,%1,%2,%3}, [%4];"
                 : "=r"(r[0]), "=r"(r[1]), "=r"(r[2]), "=r"(r[3]) : "r"(a));
}
__device__ __forceinline__ void mma_fp16(float* c, const uint32_t* a, const uint32_t* b) {
    asm volatile(
        "mma.sync.aligned.m16n8k16.row.col.f32.f16.f16.f32 "
        "{%0,%1,%2,%3}, {%4,%5,%6,%7}, {%8,%9}, {%0,%1,%2,%3};"
        : "+f"(c[0]), "+f"(c[1]), "+f"(c[2]), "+f"(c[3])
        : "r"(a[0]), "r"(a[1]), "r"(a[2]), "r"(a[3]), "r"(b[0]), "r"(b[1]));
}
__device__ __forceinline__ int ffind(int k) {
    int f = 7;
    if (k < 1152) f = 6;
    if (k < 768)  f = 5;
    if (k < 512)  f = 4;
    if (k < 320)  f = 3;
    if (k < 192)  f = 2;
    if (k < 96)   f = 1;
    if (k < 32)   f = 0;
    return f;
}

// ---------------- SMEM layout (dynamic, bytes) ----------------
#define OFF_CS  0                        // 1664*4 = 6656
#define OFF_WS  6656                     // 128*8*4 = 4096
#define OFF_AH  10752                    // 128*272 = 34816 (fp16 A tile)
#define OFF_BH  (OFF_AH + 34816)
#define SMEM_TOT (OFF_BH + 34816)        // 80384  (2 CTAs/SM)

// ---------------------------------------------------------------------------
// prep: c vector (warp per k) + fp16 pack of Wv into [n][k]
// ---------------------------------------------------------------------------
__global__ void prep_kernel(Ptrs p) {
    int tid = blockIdx.x * blockDim.x + threadIdx.x;

    if (tid < KTOT * 32) {
        int k = tid >> 5, ln = tid & 31;
        int f = ffind(k);
        int j = k - gOFFS[f];
        int d = gDIMS[f];
        const float* W = p.Wk[f];
        float s = 0.f;
        #pragma unroll
        for (int h = ln; h < HID; h += 32) s += W[h * d + j] * p.q[h];
        #pragma unroll
        for (int o = 16; o; o >>= 1) s += __shfl_xor_sync(0xffffffffu, s, o);
        if (ln == 0) g_c[k] = s * 0.08838834764831845f;
    }

    if (tid < HID * KTOT) {
        int n = tid / KTOT;
        int k = tid % KTOT;
        int f = ffind(k);
        int j = k - gOFFS[f];
        g_Bh[tid] = __float2half_rn(p.Wv[f][n * gDIMS[f] + j]);
    }
}

// ---------------------------------------------------------------------------
// main kernel: grid 256 x 256 threads, 2 CTAs/SM
// ---------------------------------------------------------------------------
__global__ void __launch_bounds__(NTHR, 2)
main_kernel(Ptrs p, float* __restrict__ out) {
    extern __shared__ char smem[];
    const uint32_t sb = smem_u32(smem);
    const int t    = threadIdx.x;
    const int lane = t & 31;
    const int wid  = t >> 5;
    const int wm   = wid >> 2;          // 0..1  (64 rows each)
    const int wn   = wid & 3;           // 0..3  (32 cols each)
    const int row0 = blockIdx.x * MBLK;

    float* cs   = (float*)(smem + OFF_CS);
    float* ws_s = (float*)(smem + OFF_WS);

    for (int i = t; i < KTOT; i += NTHR) cs[i] = g_c[i];
    __syncthreads();

    // ---- phase 1: warp-per-row scores + softmax, deferred reductions ----
    {
        #pragma unroll 1
        for (int rr = 0; rr < 16; rr++) {
            const int lrow = wid * 16 + rr;
            const int row  = row0 + lrow;
            float sc[NF];
            #pragma unroll
            for (int f = 0; f < NF; f++) {
                const int d = DIMS_C[f];
                float s = 0.f;
                #pragma unroll
                for (int j0 = 0; j0 < d; j0 += 128) {
                    int j = j0 + lane * 4;
                    if (j < d) {
                        float4 a = *(const float4*)(p.feat[f] + (size_t)row * d + j);
                        float4 b = *(const float4*)(cs + OFFS_C[f] + j);
                        s += a.x * b.x + a.y * b.y + a.z * b.z + a.w * b.w;
                    }
                }
                sc[f] = s;
            }
            #pragma unroll
            for (int f = 0; f < NF; f++) {
                #pragma unroll
                for (int o = 16; o; o >>= 1)
                    sc[f] += __shfl_xor_sync(0xffffffffu, sc[f], o);
            }
            float m = sc[0];
            #pragma unroll
            for (int f = 1; f < NF; f++) m = fmaxf(m, sc[f]);
            float sum = 0.f;
            #pragma unroll
            for (int f = 0; f < NF; f++) { sc[f] = expf(sc[f] - m); sum += sc[f]; }
            const float inv = 1.f / sum;
            if (lane == 0) {
                float4 w0 = make_float4(sc[0] * inv, sc[1] * inv, sc[2] * inv, sc[3] * inv);
                float4 w1 = make_float4(sc[4] * inv, sc[5] * inv, sc[6] * inv, sc[7] * inv);
                *(float4*)(ws_s + lrow * NF)     = w0;
                *(float4*)(ws_s + lrow * NF + 4) = w1;
                float* ao = out + (size_t)BATCHN * HID + (size_t)row * NF;
                *(float4*)(ao)     = w0;
                *(float4*)(ao + 4) = w1;
            }
        }
    }

    // ---- mainloop (REVERSE chunk order: f7 first, LIFO L2 reuse) ----
    float acc[4][4][4];
    #pragma unroll
    for (int mf = 0; mf < 4; mf++)
        #pragma unroll
        for (int nf = 0; nf < 4; nf++)
            #pragma unroll
            for (int r = 0; r < 4; r++) acc[mf][nf][r] = 0.f;

    // per-lane ldmatrix base offsets (bytes)
    const uint32_t aoff = (uint32_t)((wm * 64 + (lane & 15)) * RSTRIDE + (lane >> 4) * 16);
    const uint32_t boff = (uint32_t)((wn * 32 + ((lane >> 4) * 8) + (lane & 7)) * RSTRIDE +
                                     ((lane >> 3) & 1) * 16);
    const uint32_t sAh = sb + OFF_AH;
    const uint32_t sBh = sb + OFF_BH;

    for (int ch = 0; ch < NCH; ch++) {
        const int k0 = (NCH - 1 - ch) * KCH;   // reversed order
        __syncthreads();   // previous chunk's ldmatrix done; ws ready (iter 0)

        // --- A convert: 128 rows x 128 k, weighted fp16 (streaming 32B loads) ---
        #pragma unroll
        for (int it = 0; it < 8; it++) {
            int g   = it * 256 + t;        // 0..2047
            int row = g >> 4;
            int kq  = g & 15;              // 16 groups of 8 k
            int kg  = k0 + kq * 8;
            int f   = ffind(kg);
            int j   = kg - gOFFS[f];
            const float* src = p.feat[f] + (size_t)(row0 + row) * gDIMS[f] + j;
            float x[8];
            ldg8_stream(src, x);
            float w = ws_s[row * NF + f];
            #pragma unroll
            for (int q = 0; q < 8; q++) x[q] *= w;
            uint32_t h[4];
            #pragma unroll
            for (int q = 0; q < 4; q++) {
                __half b0 = __float2half_rn(x[2 * q]);
                __half b1 = __float2half_rn(x[2 * q + 1]);
                h[q] = (uint32_t)__half_as_ushort(b0) | ((uint32_t)__half_as_ushort(b1) << 16);
            }
            uint32_t off = (uint32_t)(row * RSTRIDE + kq * 16);
            *(uint4*)(smem + OFF_AH + off) = make_uint4(h[0], h[1], h[2], h[3]);
        }
        // --- B tile: copy from packed global (L2-resident, tiny) ---
        #pragma unroll
        for (int it = 0; it < 8; it++) {
            int g  = it * 256 + t;         // 0..2047
            int n  = g >> 4;
            int kq = g & 15;
            size_t goff = (size_t)n * KTOT + k0 + kq * 8;
            uint32_t off = (uint32_t)(n * RSTRIDE + kq * 16);
            *(uint4*)(smem + OFF_BH + off) = *(const uint4*)&g_Bh[goff];
        }
        __syncthreads();

        // --- tensor-core phase: 8 k16 steps ---
        #pragma unroll
        for (int ks = 0; ks < 8; ks++) {
            const uint32_t koff = ks * 32;   // 16 fp16 = 32 bytes
            uint32_t a[4][4];
            #pragma unroll
            for (int mf = 0; mf < 4; mf++)
                ldsm_x4(a[mf], sAh + aoff + mf * (16 * RSTRIDE) + koff);

            uint32_t bh[4][2];
            #pragma unroll
            for (int bq = 0; bq < 2; bq++) {
                uint32_t r[4];
                ldsm_x4(r, sBh + boff + bq * (16 * RSTRIDE) + koff);
                bh[bq * 2][0] = r[0]; bh[bq * 2][1] = r[1];
                bh[bq * 2 + 1][0] = r[2]; bh[bq * 2 + 1][1] = r[3];
            }
            #pragma unroll
            for (int mf = 0; mf < 4; mf++)
                #pragma unroll
                for (int nf = 0; nf < 4; nf++) mma_fp16(acc[mf][nf], a[mf], bh[nf]);
        }
    }

    // ---- epilogue: write combined ----
    #pragma unroll
    for (int mf = 0; mf < 4; mf++) {
        #pragma unroll
        for (int nf = 0; nf < 4; nf++) {
            int r0 = row0 + wm * 64 + mf * 16 + (lane >> 2);
            int c  = wn * 32 + nf * 8 + (lane & 3) * 2;
            *(float2*)(out + (size_t)r0 * HID + c) =
                make_float2(acc[mf][nf][0], acc[mf][nf][1]);
            *(float2*)(out + (size_t)(r0 + 8) * HID + c) =
                make_float2(acc[mf][nf][2], acc[mf][nf][3]);
        }
    }
}

// ---------------------------------------------------------------------------
extern "C" void kernel_launch(void* const* d_in, const int* in_sizes, int n_in,
                              void* d_out, int out_size) {
    static const int dims[NF] = {32, 64, 96, 128, 192, 256, 384, 512};
    Ptrs p;
    int wseen[NF] = {0};

    for (int i = 0; i < n_in; i++) {
        const float* ptr = (const float*)d_in[i];
        int s = in_sizes[i];
        if (s == HID) { p.q = ptr; continue; }
        bool matched = false;
        for (int f = 0; f < NF; f++)
            if (s == BATCHN * dims[f]) { p.feat[f] = ptr; matched = true; break; }
        if (matched) continue;
        for (int f = 0; f < NF; f++)
            if (s == HID * dims[f]) {
                if (!wseen[f]) { p.Wk[f] = ptr; wseen[f] = 1; }
                else           { p.Wv[f] = ptr; }
                break;
            }
    }

    cudaFuncSetAttribute(main_kernel, cudaFuncAttributeMaxDynamicSharedMemorySize, SMEM_TOT);

    prep_kernel<<<(HID * KTOT + 255) / 256, 256>>>(p);
    main_kernel<<<BATCHN / MBLK, NTHR, SMEM_TOT>>>(p, (float*)d_out);
}

// round 16
// speedup vs baseline: 1.2859x; 1.1043x over previous
#include <cuda_runtime.h>
#include <cuda_fp16.h>
#include <cstdint>

// ---------------------------------------------------------------------------
// FeatureAttentionPerFeature — mma.sync pure fp16
//   scores[b,f] = feat_f[b] . (Wk_f^T q)/sqrt(128)
//   w = softmax_f(scores)
//   combined = (w-scaled concat feats) @ Wv_all^T
// Output: [ combined (B*128) | attn_weights (B*8) ]
// R16: register-staged software pipeline — next chunk's raw A LDGs issue
// before the MMA phase and drain under it. KCH=64, double-buffered tiles,
// one barrier per chunk, 2 CTAs/SM preserved.
// ---------------------------------------------------------------------------

#define NF     8
#define HID    128
#define KTOT   1664
#define BATCHN 32768
#define MBLK   128
#define KCH    64
#define NCH    (KTOT/KCH)    // 26
#define NTHR   256
#define RSTRIDE 144          // smem tile row stride BYTES (128 data + 16 pad)

__device__ constexpr int DIMS_C[NF]   = {32, 64, 96, 128, 192, 256, 384, 512};
__device__ constexpr int OFFS_C[NF+1] = {0, 32, 96, 192, 320, 512, 768, 1152, 1664};
__constant__ int gDIMS[NF]   = {32, 64, 96, 128, 192, 256, 384, 512};
__constant__ int gOFFS[NF+1] = {0, 32, 96, 192, 320, 512, 768, 1152, 1664};

// device scratch
__device__ float g_c[KTOT];
__device__ __half g_Bh[HID * KTOT];   // Wv (fp16), [n][k] k-major

struct Ptrs {
    const float* feat[NF];
    const float* Wk[NF];
    const float* Wv[NF];
    const float* q;
};

// ---------------- helpers ----------------
__device__ __forceinline__ uint32_t smem_u32(const void* p) {
    uint32_t a;
    asm("{ .reg .u64 t; cvta.to.shared.u64 t, %1; cvt.u32.u64 %0, t; }" : "=r"(a) : "l"(p));
    return a;
}
__device__ __forceinline__ void ldsm_x4(uint32_t* r, uint32_t a) {
    asm volatile("ldmatrix.sync.aligned.m8n8.x4.shared.b16 {%0,%1,%2,%3}, [%4];"
                 : "=r"(r[0]), "=r"(r[1]), "=r"(r[2]), "=r"(r[3]) : "r"(a));
}
__device__ __forceinline__ void mma_fp16(float* c, const uint32_t* a, const uint32_t* b) {
    asm volatile(
        "mma.sync.aligned.m16n8k16.row.col.f32.f16.f16.f32 "
        "{%0,%1,%2,%3}, {%4,%5,%6,%7}, {%8,%9}, {%0,%1,%2,%3};"
        : "+f"(c[0]), "+f"(c[1]), "+f"(c[2]), "+f"(c[3])
        : "r"(a[0]), "r"(a[1]), "r"(a[2]), "r"(a[3]), "r"(b[0]), "r"(b[1]));
}
__device__ __forceinline__ int ffind(int k) {
    int f = 7;
    if (k < 1152) f = 6;
    if (k < 768)  f = 5;
    if (k < 512)  f = 4;
    if (k < 320)  f = 3;
    if (k < 192)  f = 2;
    if (k < 96)   f = 1;
    if (k < 32)   f = 0;
    return f;
}

// ---------------- SMEM layout (dynamic, bytes) ----------------
#define OFF_CS  0                        // 1664*4 = 6656
#define OFF_WS  6656                     // 128*8*4 = 4096
#define OFF_A0  10752                    // 128*144 = 18432
#define OFF_A1  (OFF_A0 + 18432)
#define OFF_B0  (OFF_A1 + 18432)
#define OFF_B1  (OFF_B0 + 18432)
#define SMEM_TOT (OFF_B1 + 18432)        // 84480 (2 CTAs/SM)

// ---------------------------------------------------------------------------
// prep: c vector (warp per k) + fp16 pack of Wv into [n][k]
// ---------------------------------------------------------------------------
__global__ void prep_kernel(Ptrs p) {
    int tid = blockIdx.x * blockDim.x + threadIdx.x;

    if (tid < KTOT * 32) {
        int k = tid >> 5, ln = tid & 31;
        int f = ffind(k);
        int j = k - gOFFS[f];
        int d = gDIMS[f];
        const float* W = p.Wk[f];
        float s = 0.f;
        #pragma unroll
        for (int h = ln; h < HID; h += 32) s += W[h * d + j] * p.q[h];
        #pragma unroll
        for (int o = 16; o; o >>= 1) s += __shfl_xor_sync(0xffffffffu, s, o);
        if (ln == 0) g_c[k] = s * 0.08838834764831845f;
    }

    if (tid < HID * KTOT) {
        int n = tid / KTOT;
        int k = tid % KTOT;
        int f = ffind(k);
        int j = k - gOFFS[f];
        g_Bh[tid] = __float2half_rn(p.Wv[f][n * gDIMS[f] + j]);
    }
}

// ---------------------------------------------------------------------------
// main kernel: grid 256 x 256 threads, 2 CTAs/SM
// ---------------------------------------------------------------------------
__global__ void __launch_bounds__(NTHR, 2)
main_kernel(Ptrs p, float* __restrict__ out) {
    extern __shared__ char smem[];
    const uint32_t sb = smem_u32(smem);
    const int t    = threadIdx.x;
    const int lane = t & 31;
    const int wid  = t >> 5;
    const int wm   = wid >> 2;          // 0..1  (64 rows each)
    const int wn   = wid & 3;           // 0..3  (32 cols each)
    const int row0 = blockIdx.x * MBLK;

    float* cs   = (float*)(smem + OFF_CS);
    float* ws_s = (float*)(smem + OFF_WS);

    for (int i = t; i < KTOT; i += NTHR) cs[i] = g_c[i];
    __syncthreads();

    // ---- phase 1: warp-per-row scores + softmax, deferred reductions ----
    {
        #pragma unroll 1
        for (int rr = 0; rr < 16; rr++) {
            const int lrow = wid * 16 + rr;
            const int row  = row0 + lrow;
            float sc[NF];
            #pragma unroll
            for (int f = 0; f < NF; f++) {
                const int d = DIMS_C[f];
                float s = 0.f;
                #pragma unroll
                for (int j0 = 0; j0 < d; j0 += 128) {
                    int j = j0 + lane * 4;
                    if (j < d) {
                        float4 a = *(const float4*)(p.feat[f] + (size_t)row * d + j);
                        float4 b = *(const float4*)(cs + OFFS_C[f] + j);
                        s += a.x * b.x + a.y * b.y + a.z * b.z + a.w * b.w;
                    }
                }
                sc[f] = s;
            }
            #pragma unroll
            for (int f = 0; f < NF; f++) {
                #pragma unroll
                for (int o = 16; o; o >>= 1)
                    sc[f] += __shfl_xor_sync(0xffffffffu, sc[f], o);
            }
            float m = sc[0];
            #pragma unroll
            for (int f = 1; f < NF; f++) m = fmaxf(m, sc[f]);
            float sum = 0.f;
            #pragma unroll
            for (int f = 0; f < NF; f++) { sc[f] = expf(sc[f] - m); sum += sc[f]; }
            const float inv = 1.f / sum;
            if (lane == 0) {
                float4 w0 = make_float4(sc[0] * inv, sc[1] * inv, sc[2] * inv, sc[3] * inv);
                float4 w1 = make_float4(sc[4] * inv, sc[5] * inv, sc[6] * inv, sc[7] * inv);
                *(float4*)(ws_s + lrow * NF)     = w0;
                *(float4*)(ws_s + lrow * NF + 4) = w1;
                float* ao = out + (size_t)BATCHN * HID + (size_t)row * NF;
                *(float4*)(ao)     = w0;
                *(float4*)(ao + 4) = w1;
            }
        }
    }
    __syncthreads();   // ws_s visible to all before mainloop converts

    // ---- mainloop: register-staged pipeline ----
    float acc[4][4][4];
    #pragma unroll
    for (int mf = 0; mf < 4; mf++)
        #pragma unroll
        for (int nf = 0; nf < 4; nf++)
            #pragma unroll
            for (int r = 0; r < 4; r++) acc[mf][nf][r] = 0.f;

    const uint32_t aoff = (uint32_t)((wm * 64 + (lane & 15)) * RSTRIDE + (lane >> 4) * 16);
    const uint32_t boff = (uint32_t)((wn * 32 + ((lane >> 4) * 8) + (lane & 7)) * RSTRIDE +
                                     ((lane >> 3) & 1) * 16);

    // raw A staging registers: 4 groups x 8 floats (chunk = 64 k)
    float4 v[4][2];

    // prologue: load chunk 0 raw
    #pragma unroll
    for (int it = 0; it < 4; it++) {
        int g   = it * 256 + t;        // 0..1023
        int row = g >> 3;
        int kq  = g & 7;
        int kg  = 0 + kq * 8;
        int f   = ffind(kg);
        int j   = kg - gOFFS[f];
        const float* src = p.feat[f] + (size_t)(row0 + row) * gDIMS[f] + j;
        v[it][0] = *(const float4*)src;
        v[it][1] = *(const float4*)(src + 4);
    }

    #pragma unroll 1
    for (int ch = 0; ch < NCH; ch++) {
        const int buf = ch & 1;
        const uint32_t offA = buf ? OFF_A1 : OFF_A0;
        const uint32_t offB = buf ? OFF_B1 : OFF_B0;
        const int k0 = ch * KCH;

        // --- convert held regs -> weighted fp16 A tile; copy B tile ---
        #pragma unroll
        for (int it = 0; it < 4; it++) {
            int g   = it * 256 + t;
            int row = g >> 3;
            int kq  = g & 7;
            int f   = ffind(k0 + kq * 8);
            float w = ws_s[row * NF + f];
            float x[8] = {v[it][0].x * w, v[it][0].y * w, v[it][0].z * w, v[it][0].w * w,
                          v[it][1].x * w, v[it][1].y * w, v[it][1].z * w, v[it][1].w * w};
            uint32_t h[4];
            #pragma unroll
            for (int q = 0; q < 4; q++) {
                __half b0 = __float2half_rn(x[2 * q]);
                __half b1 = __float2half_rn(x[2 * q + 1]);
                h[q] = (uint32_t)__half_as_ushort(b0) | ((uint32_t)__half_as_ushort(b1) << 16);
            }
            uint32_t off = (uint32_t)(row * RSTRIDE + kq * 16);
            *(uint4*)(smem + offA + off) = make_uint4(h[0], h[1], h[2], h[3]);
        }
        #pragma unroll
        for (int it = 0; it < 4; it++) {
            int g  = it * 256 + t;
            int n  = g >> 3;
            int kq = g & 7;
            size_t goff = (size_t)n * KTOT + k0 + kq * 8;
            uint32_t off = (uint32_t)(n * RSTRIDE + kq * 16);
            *(uint4*)(smem + offB + off) = *(const uint4*)&g_Bh[goff];
        }
        __syncthreads();   // tile ch ready; MMA(ch-1) finished (program order)

        // --- issue raw A loads for chunk ch+1 (drain under MMA below) ---
        if (ch + 1 < NCH) {
            const int k1 = (ch + 1) * KCH;
            #pragma unroll
            for (int it = 0; it < 4; it++) {
                int g   = it * 256 + t;
                int row = g >> 3;
                int kq  = g & 7;
                int kg  = k1 + kq * 8;
                int f   = ffind(kg);
                int j   = kg - gOFFS[f];
                const float* src = p.feat[f] + (size_t)(row0 + row) * gDIMS[f] + j;
                v[it][0] = *(const float4*)src;
                v[it][1] = *(const float4*)(src + 4);
            }
        }

        // --- tensor-core phase: 4 k16 steps ---
        const uint32_t sA = sb + offA;
        const uint32_t sB = sb + offB;
        #pragma unroll
        for (int ks = 0; ks < 4; ks++) {
            const uint32_t koff = ks * 32;   // 16 fp16 = 32 bytes
            uint32_t a[4][4];
            #pragma unroll
            for (int mf = 0; mf < 4; mf++)
                ldsm_x4(a[mf], sA + aoff + mf * (16 * RSTRIDE) + koff);

            uint32_t bh[4][2];
            #pragma unroll
            for (int bq = 0; bq < 2; bq++) {
                uint32_t r[4];
                ldsm_x4(r, sB + boff + bq * (16 * RSTRIDE) + koff);
                bh[bq * 2][0] = r[0]; bh[bq * 2][1] = r[1];
                bh[bq * 2 + 1][0] = r[2]; bh[bq * 2 + 1][1] = r[3];
            }
            #pragma unroll
            for (int mf = 0; mf < 4; mf++)
                #pragma unroll
                for (int nf = 0; nf < 4; nf++) mma_fp16(acc[mf][nf], a[mf], bh[nf]);
        }
    }

    // ---- epilogue: write combined ----
    #pragma unroll
    for (int mf = 0; mf < 4; mf++) {
        #pragma unroll
        for (int nf = 0; nf < 4; nf++) {
            int r0 = row0 + wm * 64 + mf * 16 + (lane >> 2);
            int c  = wn * 32 + nf * 8 + (lane & 3) * 2;
            *(float2*)(out + (size_t)r0 * HID + c) =
                make_float2(acc[mf][nf][0], acc[mf][nf][1]);
            *(float2*)(out + (size_t)(r0 + 8) * HID + c) =
                make_float2(acc[mf][nf][2], acc[mf][nf][3]);
        }
    }
}

// ---------------------------------------------------------------------------
extern "C" void kernel_launch(void* const* d_in, const int* in_sizes, int n_in,
                              void* d_out, int out_size) {
    static const int dims[NF] = {32, 64, 96, 128, 192, 256, 384, 512};
    Ptrs p;
    int wseen[NF] = {0};

    for (int i = 0; i < n_in; i++) {
        const float* ptr = (const float*)d_in[i];
        int s = in_sizes[i];
        if (s == HID) { p.q = ptr; continue; }
        bool matched = false;
        for (int f = 0; f < NF; f++)
            if (s == BATCHN * dims[f]) { p.feat[f] = ptr; matched = true; break; }
        if (matched) continue;
        for (int f = 0; f < NF; f++)
            if (s == HID * dims[f]) {
                if (!wseen[f]) { p.Wk[f] = ptr; wseen[f] = 1; }
                else           { p.Wv[f] = ptr; }
                break;
            }
    }

    cudaFuncSetAttribute(main_kernel, cudaFuncAttributeMaxDynamicSharedMemorySize, SMEM_TOT);

    prep_kernel<<<(HID * KTOT + 255) / 256, 256>>>(p);
    main_kernel<<<BATCHN / MBLK, NTHR, SMEM_TOT>>>(p, (float*)d_out);
}

// round 17
// speedup vs baseline: 1.3322x; 1.0360x over previous
#include <cuda_runtime.h>
#include <cuda_fp16.h>
#include <cstdint>

// ---------------------------------------------------------------------------
// FeatureAttentionPerFeature — mma.sync pure fp16
//   scores[b,f] = feat_f[b] . (Wk_f^T q)/sqrt(128)
//   w = softmax_f(scores)
//   combined = (w-scaled concat feats) @ Wv_all^T
// Output: [ combined (B*128) | attn_weights (B*8) ]
// R17 (on R12): B tiles staged via cp.async.cg (L1-bypass, merged LDG+STS),
// packed f16x2 converts. Numerics identical to R12.
// ---------------------------------------------------------------------------

#define NF     8
#define HID    128
#define KTOT   1664
#define BATCHN 32768
#define MBLK   128
#define KCH    128
#define NCH    (KTOT/KCH)    // 13
#define NTHR   256
#define RSTRIDE 272          // smem row stride BYTES (256 data + 16 pad)

__device__ constexpr int DIMS_C[NF]   = {32, 64, 96, 128, 192, 256, 384, 512};
__device__ constexpr int OFFS_C[NF+1] = {0, 32, 96, 192, 320, 512, 768, 1152, 1664};
__constant__ int gDIMS[NF]   = {32, 64, 96, 128, 192, 256, 384, 512};
__constant__ int gOFFS[NF+1] = {0, 32, 96, 192, 320, 512, 768, 1152, 1664};

// device scratch
__device__ float g_c[KTOT];
__device__ __half g_Bh[HID * KTOT];   // Wv (fp16), [n][k] k-major

struct Ptrs {
    const float* feat[NF];
    const float* Wk[NF];
    const float* Wv[NF];
    const float* q;
};

// ---------------- helpers ----------------
__device__ __forceinline__ uint32_t smem_u32(const void* p) {
    uint32_t a;
    asm("{ .reg .u64 t; cvta.to.shared.u64 t, %1; cvt.u32.u64 %0, t; }" : "=r"(a) : "l"(p));
    return a;
}
__device__ __forceinline__ void ldsm_x4(uint32_t* r, uint32_t a) {
    asm volatile("ldmatrix.sync.aligned.m8n8.x4.shared.b16 {%0,%1,%2,%3}, [%4];"
                 : "=r"(r[0]), "=r"(r[1]), "=r"(r[2]), "=r"(r[3]) : "r"(a));
}
__device__ __forceinline__ void mma_fp16(float* c, const uint32_t* a, const uint32_t* b) {
    asm volatile(
        "mma.sync.aligned.m16n8k16.row.col.f32.f16.f16.f32 "
        "{%0,%1,%2,%3}, {%4,%5,%6,%7}, {%8,%9}, {%0,%1,%2,%3};"
        : "+f"(c[0]), "+f"(c[1]), "+f"(c[2]), "+f"(c[3])
        : "r"(a[0]), "r"(a[1]), "r"(a[2]), "r"(a[3]), "r"(b[0]), "r"(b[1]));
}
__device__ __forceinline__ void cpa16(uint32_t dst, const void* src) {
    asm volatile("cp.async.cg.shared.global [%0], [%1], 16;" :: "r"(dst), "l"(src));
}
__device__ __forceinline__ void cpa_commit() {
    asm volatile("cp.async.commit_group;" ::: "memory");
}
__device__ __forceinline__ void cpa_wait0() {
    asm volatile("cp.async.wait_group 0;" ::: "memory");
}
__device__ __forceinline__ int ffind(int k) {
    int f = 7;
    if (k < 1152) f = 6;
    if (k < 768)  f = 5;
    if (k < 512)  f = 4;
    if (k < 320)  f = 3;
    if (k < 192)  f = 2;
    if (k < 96)   f = 1;
    if (k < 32)   f = 0;
    return f;
}

// ---------------- SMEM layout (dynamic, bytes) ----------------
#define OFF_CS  0                        // 1664*4 = 6656
#define OFF_WS  6656                     // 128*8*4 = 4096
#define OFF_AH  10752                    // 128*272 = 34816 (fp16 A tile)
#define OFF_BH  (OFF_AH + 34816)
#define SMEM_TOT (OFF_BH + 34816)        // 80384  (2 CTAs/SM)

// ---------------------------------------------------------------------------
// prep: c vector (warp per k) + fp16 pack of Wv into [n][k]
// ---------------------------------------------------------------------------
__global__ void prep_kernel(Ptrs p) {
    int tid = blockIdx.x * blockDim.x + threadIdx.x;

    if (tid < KTOT * 32) {
        int k = tid >> 5, ln = tid & 31;
        int f = ffind(k);
        int j = k - gOFFS[f];
        int d = gDIMS[f];
        const float* W = p.Wk[f];
        float s = 0.f;
        #pragma unroll
        for (int h = ln; h < HID; h += 32) s += W[h * d + j] * p.q[h];
        #pragma unroll
        for (int o = 16; o; o >>= 1) s += __shfl_xor_sync(0xffffffffu, s, o);
        if (ln == 0) g_c[k] = s * 0.08838834764831845f;
    }

    if (tid < HID * KTOT) {
        int n = tid / KTOT;
        int k = tid % KTOT;
        int f = ffind(k);
        int j = k - gOFFS[f];
        g_Bh[tid] = __float2half_rn(p.Wv[f][n * gDIMS[f] + j]);
    }
}

// ---------------------------------------------------------------------------
// main kernel: grid 256 x 256 threads, 2 CTAs/SM
// ---------------------------------------------------------------------------
__global__ void __launch_bounds__(NTHR, 2)
main_kernel(Ptrs p, float* __restrict__ out) {
    extern __shared__ char smem[];
    const uint32_t sb = smem_u32(smem);
    const int t    = threadIdx.x;
    const int lane = t & 31;
    const int wid  = t >> 5;
    const int wm   = wid >> 2;          // 0..1  (64 rows each)
    const int wn   = wid & 3;           // 0..3  (32 cols each)
    const int row0 = blockIdx.x * MBLK;

    float* cs   = (float*)(smem + OFF_CS);
    float* ws_s = (float*)(smem + OFF_WS);

    for (int i = t; i < KTOT; i += NTHR) cs[i] = g_c[i];
    __syncthreads();

    // ---- phase 1: warp-per-row scores + softmax, deferred reductions ----
    {
        #pragma unroll 1
        for (int rr = 0; rr < 16; rr++) {
            const int lrow = wid * 16 + rr;
            const int row  = row0 + lrow;
            float sc[NF];
            #pragma unroll
            for (int f = 0; f < NF; f++) {
                const int d = DIMS_C[f];
                float s = 0.f;
                #pragma unroll
                for (int j0 = 0; j0 < d; j0 += 128) {
                    int j = j0 + lane * 4;
                    if (j < d) {
                        float4 a = *(const float4*)(p.feat[f] + (size_t)row * d + j);
                        float4 b = *(const float4*)(cs + OFFS_C[f] + j);
                        s += a.x * b.x + a.y * b.y + a.z * b.z + a.w * b.w;
                    }
                }
                sc[f] = s;
            }
            #pragma unroll
            for (int f = 0; f < NF; f++) {
                #pragma unroll
                for (int o = 16; o; o >>= 1)
                    sc[f] += __shfl_xor_sync(0xffffffffu, sc[f], o);
            }
            float m = sc[0];
            #pragma unroll
            for (int f = 1; f < NF; f++) m = fmaxf(m, sc[f]);
            float sum = 0.f;
            #pragma unroll
            for (int f = 0; f < NF; f++) { sc[f] = expf(sc[f] - m); sum += sc[f]; }
            const float inv = 1.f / sum;
            if (lane == 0) {
                float4 w0 = make_float4(sc[0] * inv, sc[1] * inv, sc[2] * inv, sc[3] * inv);
                float4 w1 = make_float4(sc[4] * inv, sc[5] * inv, sc[6] * inv, sc[7] * inv);
                *(float4*)(ws_s + lrow * NF)     = w0;
                *(float4*)(ws_s + lrow * NF + 4) = w1;
                float* ao = out + (size_t)BATCHN * HID + (size_t)row * NF;
                *(float4*)(ao)     = w0;
                *(float4*)(ao + 4) = w1;
            }
        }
    }

    // ---- mainloop ----
    float acc[4][4][4];
    #pragma unroll
    for (int mf = 0; mf < 4; mf++)
        #pragma unroll
        for (int nf = 0; nf < 4; nf++)
            #pragma unroll
            for (int r = 0; r < 4; r++) acc[mf][nf][r] = 0.f;

    // per-lane ldmatrix base offsets (bytes)
    const uint32_t aoff = (uint32_t)((wm * 64 + (lane & 15)) * RSTRIDE + (lane >> 4) * 16);
    const uint32_t boff = (uint32_t)((wn * 32 + ((lane >> 4) * 8) + (lane & 7)) * RSTRIDE +
                                     ((lane >> 3) & 1) * 16);
    const uint32_t sAh = sb + OFF_AH;
    const uint32_t sBh = sb + OFF_BH;

    for (int ch = 0; ch < NCH; ch++) {
        const int k0 = ch * KCH;
        __syncthreads();   // previous chunk's ldmatrix done; ws ready (iter 0)

        // --- B tile: cp.async L2->smem (bypasses L1), drains under A convert ---
        #pragma unroll
        for (int it = 0; it < 8; it++) {
            int g  = it * 256 + t;         // 0..2047
            int n  = g >> 4;
            int kq = g & 15;
            size_t goff = (size_t)n * KTOT + k0 + kq * 8;
            uint32_t off = (uint32_t)(n * RSTRIDE + kq * 16);
            cpa16(sBh + off, &g_Bh[goff]);
        }
        cpa_commit();

        // --- A convert: 128 rows x 128 k, weighted fp16 (packed cvt) ---
        #pragma unroll
        for (int it = 0; it < 8; it++) {
            int g   = it * 256 + t;        // 0..2047
            int row = g >> 4;
            int kq  = g & 15;              // 16 groups of 8 k
            int kg  = k0 + kq * 8;
            int f   = ffind(kg);
            int j   = kg - gOFFS[f];
            const float* src = p.feat[f] + (size_t)(row0 + row) * gDIMS[f] + j;
            float4 v0 = *(const float4*)src;
            float4 v1 = *(const float4*)(src + 4);
            float w = ws_s[row * NF + f];
            float x[8] = {v0.x * w, v0.y * w, v0.z * w, v0.w * w,
                          v1.x * w, v1.y * w, v1.z * w, v1.w * w};
            uint32_t h[4];
            #pragma unroll
            for (int q = 0; q < 4; q++) {
                __half2 hh = __floats2half2_rn(x[2 * q], x[2 * q + 1]);
                h[q] = *(uint32_t*)&hh;
            }
            uint32_t off = (uint32_t)(row * RSTRIDE + kq * 16);
            *(uint4*)(smem + OFF_AH + off) = make_uint4(h[0], h[1], h[2], h[3]);
        }

        cpa_wait0();       // B landed
        __syncthreads();

        // --- tensor-core phase: 8 k16 steps ---
        #pragma unroll
        for (int ks = 0; ks < 8; ks++) {
            const uint32_t koff = ks * 32;   // 16 fp16 = 32 bytes
            uint32_t a[4][4];
            #pragma unroll
            for (int mf = 0; mf < 4; mf++)
                ldsm_x4(a[mf], sAh + aoff + mf * (16 * RSTRIDE) + koff);

            uint32_t bh[4][2];
            #pragma unroll
            for (int bq = 0; bq < 2; bq++) {
                uint32_t r[4];
                ldsm_x4(r, sBh + boff + bq * (16 * RSTRIDE) + koff);
                bh[bq * 2][0] = r[0]; bh[bq * 2][1] = r[1];
                bh[bq * 2 + 1][0] = r[2]; bh[bq * 2 + 1][1] = r[3];
            }
            #pragma unroll
            for (int mf = 0; mf < 4; mf++)
                #pragma unroll
                for (int nf = 0; nf < 4; nf++) mma_fp16(acc[mf][nf], a[mf], bh[nf]);
        }
    }

    // ---- epilogue: write combined ----
    #pragma unroll
    for (int mf = 0; mf < 4; mf++) {
        #pragma unroll
        for (int nf = 0; nf < 4; nf++) {
            int r0 = row0 + wm * 64 + mf * 16 + (lane >> 2);
            int c  = wn * 32 + nf * 8 + (lane & 3) * 2;
            *(float2*)(out + (size_t)r0 * HID + c) =
                make_float2(acc[mf][nf][0], acc[mf][nf][1]);
            *(float2*)(out + (size_t)(r0 + 8) * HID + c) =
                make_float2(acc[mf][nf][2], acc[mf][nf][3]);
        }
    }
}

// ---------------------------------------------------------------------------
extern "C" void kernel_launch(void* const* d_in, const int* in_sizes, int n_in,
                              void* d_out, int out_size) {
    static const int dims[NF] = {32, 64, 96, 128, 192, 256, 384, 512};
    Ptrs p;
    int wseen[NF] = {0};

    for (int i = 0; i < n_in; i++) {
        const float* ptr = (const float*)d_in[i];
        int s = in_sizes[i];
        if (s == HID) { p.q = ptr; continue; }
        bool matched = false;
        for (int f = 0; f < NF; f++)
            if (s == BATCHN * dims[f]) { p.feat[f] = ptr; matched = true; break; }
        if (matched) continue;
        for (int f = 0; f < NF; f++)
            if (s == HID * dims[f]) {
                if (!wseen[f]) { p.Wk[f] = ptr; wseen[f] = 1; }
                else           { p.Wv[f] = ptr; }
                break;
            }
    }

    cudaFuncSetAttribute(main_kernel, cudaFuncAttributeMaxDynamicSharedMemorySize, SMEM_TOT);

    prep_kernel<<<(HID * KTOT + 255) / 256, 256>>>(p);
    main_kernel<<<BATCHN / MBLK, NTHR, SMEM_TOT>>>(p, (float*)d_out);
}